// round 9
// baseline (speedup 1.0000x reference)
#include <cuda_runtime.h>
#include <cuda_pipeline.h>
#include <math.h>

#define NB 16
#define TT 12
#define AL 0.2f
#define NBLK 128

// Dynamic smem (floats): s_W[4096] | {src,own}[j] for j=0..2
#define DYN_FLOATS (4096 * 7)
#define DYN_BYTES (DYN_FLOATS * 4)

__global__ __launch_bounds__(256) void gat_pipe(
    const float* __restrict__ inp,   // [NB,TT,64,64]
    const float* __restrict__ W,     // [64,64]
    const float* __restrict__ a,     // [128]
    float* __restrict__ out_elu,
    float* __restrict__ out_att,
    int write_att)
{
    extern __shared__ float sm[];
    float* s_W = sm;                 // 64x64

    __shared__ __align__(16) float s_a [128];
    __shared__ __align__(16) float s_WA[192];   // WAlo | WAhi | WA1
    __shared__ __align__(16) float s_cs[128];
    __shared__ __align__(16) float s_g [128];   // g1[64] or g2a[64]|g2b[64]
    __shared__ __align__(16) float s_SW[128];
    __shared__ __align__(16) float s_p0[32], s_p1[32];
    __shared__ __align__(16) float s_att[32];
    __shared__ __align__(16) float s_wc[64], s_q[64];

    const int t = threadIdx.x, b = blockIdx.x;

    // ---- issue ALL prefetches up front (3 groups) ----
    {
        const float4* Wg = (const float4*)W;
        float4* Ws = (float4*)s_W;
#pragma unroll
        for (int i = 0; i < 4; i++)
            __pipeline_memcpy_async(&Ws[t + i * 256], &Wg[t + i * 256], 16);
        if (t < 32)
            __pipeline_memcpy_async(&((float4*)s_a)[t], &((const float4*)a)[t], 16);
    }
#pragma unroll
    for (int j = 0; j < 3; j++) {
        const int tl = b + NBLK * j;
        const int pair = tl >> 1, vb = tl & 1;
        const int n = pair / TT, ti = pair - n * TT;
        const int sl = (ti < 6) ? (2 * ti + vb) : (2 * (ti - 6) + vb);
        const float4* s4 = (const float4*)(inp + (size_t)(n * TT + sl) * 4096);
        const float4* o4 = (const float4*)(inp + (size_t)pair * 4096);
        float4* ds = (float4*)(sm + 4096 * (1 + 2 * j));
        float4* dn = (float4*)(sm + 4096 * (2 + 2 * j));
#pragma unroll
        for (int i = 0; i < 4; i++) {
            __pipeline_memcpy_async(&ds[t + i * 256], &s4[t + i * 256], 16);
            __pipeline_memcpy_async(&dn[t + i * 256], &o4[t + i * 256], 16);
        }
        __pipeline_commit();
    }

    __pipeline_wait_prior(2);        // group 0 (W, a, tile0) complete
    __syncthreads();

    // ---- WA stage (once per block): lo | hi | lo+hi ----
    if (t < 192) {
        const int c = t >> 6, k = t & 63;
        float s0 = 0.f, s1 = 0.f;
#pragma unroll
        for (int j0 = 0; j0 < 64; j0 += 2) {
            const int ja = (j0 + k) & 63, jb = (j0 + 1 + k) & 63;
            const float aa = (c == 0) ? s_a[ja] : (c == 1) ? s_a[64 + ja]
                                                 : (s_a[ja] + s_a[64 + ja]);
            const float ab = (c == 0) ? s_a[jb] : (c == 1) ? s_a[64 + jb]
                                                 : (s_a[jb] + s_a[64 + jb]);
            s0 = fmaf(s_W[k * 64 + ja], aa, s0);
            s1 = fmaf(s_W[k * 64 + jb], ab, s1);
        }
        s_WA[c * 64 + k] = s0 + s1;
    }
    __syncthreads();

    // ---- 3 tiles ----
    for (int j = 0; j < 3; j++) {
        if (j) { __pipeline_wait_prior(2 - j); __syncthreads(); }
        const int tl = b + NBLK * j;
        const int pair = tl >> 1, vb = tl & 1;
        const int n = pair / TT, ti = pair - n * TT;
        float* bs = sm + 4096 * (1 + 2 * j);    // src slab
        float* bo = sm + 4096 * (2 + 2 * j);    // own slab
        float4* oe4 = (float4*)(out_elu + (size_t)pair * 4096 + vb * 2048);
        float4* oa4 = (float4*)(out_att + (size_t)pair * 4096 + vb * 2048);

        if (ti < 6) {
            // s1: own half colsums (t<128)  ||  g1 dots (t>=128, 2 thr/row)
            if (t < 128) {
                const int hb = t >> 6, k = t & 63;
                const float* p = bo + hb * 2048 + k;
                float c0 = 0.f, c1 = 0.f, c2 = 0.f, c3 = 0.f;
#pragma unroll
                for (int w = 0; w < 32; w += 4) {
                    c0 += p[w * 64];       c1 += p[(w + 1) * 64];
                    c2 += p[(w + 2) * 64]; c3 += p[(w + 3) * 64];
                }
                s_cs[t] = (c0 + c1) + (c2 + c3);
            } else {
                const int d = t - 128, u = d >> 1, p = d & 1;
                const float* wa1 = s_WA + 128;
                float s0 = 0.f, s1v = 0.f;
#pragma unroll
                for (int i = 0; i < 32; i += 2) {
                    const int ka = (2 * i + p + 2 * u) & 63;
                    const int kb = (2 * (i + 1) + p + 2 * u) & 63;
                    s0  = fmaf(bs[u * 64 + ka], wa1[ka], s0);
                    s1v = fmaf(bs[u * 64 + kb], wa1[kb], s1v);
                }
                float s = s0 + s1v;
                s += __shfl_xor_sync(0xffffffffu, s, 1);
                if (!p) s_g[u] = s;
            }
            __syncthreads();
            // s2: SW_c[j] = cs_c . W[:,j]  (256 threads, 2 thr/dot)
            {
                const int d = t >> 1, p = t & 1, c = d >> 6, jj = d & 63;
                const float* cs = s_cs + c * 64;
                float s0 = 0.f, s1v = 0.f;
#pragma unroll
                for (int i = 0; i < 32; i += 2) {
                    const int ka = p * 32 + i, kb = ka + 1;
                    s0  = fmaf(cs[ka], s_W[ka * 64 + jj], s0);
                    s1v = fmaf(cs[kb], s_W[kb * 64 + jj], s1v);
                }
                float s = s0 + s1v;
                s += __shfl_xor_sync(0xffffffffu, s, 1);
                if (!p) s_SW[c * 64 + jj] = s;
            }
            __syncthreads();
            // s3: closed-form softmax
            if (t < 32) {
                float e0 = s_g[2 * t], e1 = s_g[2 * t + 1];
                e0 = (e0 > 0.f) ? e0 : AL * e0;
                e1 = (e1 > 0.f) ? e1 : AL * e1;
                const float m = fmaxf(e0, e1);
                const float p0 = __expf(e0 - m), p1 = __expf(e1 - m);
                const float inv = __frcp_rn(32.f * (p0 + p1));
                s_p0[t] = p0 * inv;
                s_p1[t] = p1 * inv;
            }
            __syncthreads();
            // s4: outputs
            const float4* Qlo = (const float4*)s_SW;
            const float4* Qhi = (const float4*)(s_SW + 64);
#pragma unroll
            for (int i = 0; i < 2; i++) {
                const int idx4 = t + i * 256;
                const int r = idx4 >> 4, w4 = idx4 & 15;
                const float a0 = s_p0[r], a1 = s_p1[r];
                const float4 q0 = Qlo[w4], q1 = Qhi[w4];
                float4 rr;
                rr.x = fmaf(a0, q0.x, a1 * q1.x);
                rr.y = fmaf(a0, q0.y, a1 * q1.y);
                rr.z = fmaf(a0, q0.z, a1 * q1.z);
                rr.w = fmaf(a0, q0.w, a1 * q1.w);
                rr.x = (rr.x > 0.f) ? rr.x : (__expf(rr.x) - 1.f);
                rr.y = (rr.y > 0.f) ? rr.y : (__expf(rr.y) - 1.f);
                rr.z = (rr.z > 0.f) ? rr.z : (__expf(rr.z) - 1.f);
                rr.w = (rr.w > 0.f) ? rr.w : (__expf(rr.w) - 1.f);
                oe4[idx4] = rr;
                if (write_att) {
                    const float av = (w4 < 8) ? a0 : a1;
                    oa4[idx4] = make_float4(av, av, av, av);
                }
            }
        } else {
            // s1: g2a | g2b dots (256 threads, 2 thr/dot)
            {
                const int d = t >> 1, p = t & 1, c = d >> 6, u = d & 63;
                const float* wav = s_WA + c * 64;
                float s0 = 0.f, s1v = 0.f;
#pragma unroll
                for (int i = 0; i < 32; i += 2) {
                    const int ka = (2 * i + p + 2 * u) & 63;
                    const int kb = (2 * (i + 1) + p + 2 * u) & 63;
                    s0  = fmaf(bs[u * 64 + ka], wav[ka], s0);
                    s1v = fmaf(bs[u * 64 + kb], wav[kb], s1v);
                }
                float s = s0 + s1v;
                s += __shfl_xor_sync(0xffffffffu, s, 1);
                if (!p) s_g[c * 64 + u] = s;
            }
            __syncthreads();
            // s2: 32-wide softmax (warp 0)
            if (t < 32) {
                float e = s_g[2 * t] + s_g[64 + 2 * t + 1];
                e = (e > 0.f) ? e : AL * e;
                float m = e;
#pragma unroll
                for (int o = 16; o; o >>= 1) m = fmaxf(m, __shfl_xor_sync(0xffffffffu, m, o));
                const float p = __expf(e - m);
                float ss = p;
#pragma unroll
                for (int o = 16; o; o >>= 1) ss += __shfl_xor_sync(0xffffffffu, ss, o);
                s_att[t] = p * __frcp_rn(2.f * ss);
            }
            __syncthreads();
            // s3: weighted colsum of own (t<128, 2 thr/col)
            if (t < 128) {
                const int k = t >> 1, p = t & 1;
                float s0 = 0.f, s1v = 0.f;
#pragma unroll
                for (int i = 0; i < 16; i += 2) {
                    const int w = p * 16 + i;
                    s0  = fmaf(s_att[w],     bo[w * 64 + k] + bo[(w + 32) * 64 + k], s0);
                    s1v = fmaf(s_att[w + 1], bo[(w + 1) * 64 + k] + bo[(w + 33) * 64 + k], s1v);
                }
                float s = s0 + s1v;
                s += __shfl_xor_sync(0xffffffffu, s, 1);
                if (!p) s_wc[k] = s;
            }
            __syncthreads();
            // s4: q[j] = wc . W[:,j], fold ELU (t<128, 2 thr/dot)
            if (t < 128) {
                const int jj = t >> 1, p = t & 1;
                float s0 = 0.f, s1v = 0.f;
#pragma unroll
                for (int i = 0; i < 32; i += 2) {
                    const int ka = p * 32 + i, kb = ka + 1;
                    s0  = fmaf(s_wc[ka], s_W[ka * 64 + jj], s0);
                    s1v = fmaf(s_wc[kb], s_W[kb * 64 + jj], s1v);
                }
                float s = s0 + s1v;
                s += __shfl_xor_sync(0xffffffffu, s, 1);
                if (!p) s_q[jj] = (s > 0.f) ? s : (__expf(s) - 1.f);
            }
            __syncthreads();
            // s5: broadcast outputs
            const float4* Q4 = (const float4*)s_q;
            const float4* A4 = (const float4*)s_att;
#pragma unroll
            for (int i = 0; i < 2; i++) {
                const int idx4 = t + i * 256, w4 = idx4 & 15;
                oe4[idx4] = Q4[w4];
                if (write_att) oa4[idx4] = A4[w4 & 7];
            }
        }
        __syncthreads();             // tile boundary
    }
}

extern "C" void kernel_launch(void* const* d_in, const int* in_sizes, int n_in,
                              void* d_out, int out_size)
{
    const float* inp = (const float*)d_in[0];   // [16,12,64,64]
    // d_in[1] = adj — dead in the reference
    const float* W   = (const float*)d_in[2];   // [64,64]
    const float* a   = (const float*)d_in[3];   // [128,1]
    float* out = (float*)d_out;

    const int elu_elems = NB * TT * 64 * 64;    // 786432
    const int write_att = (out_size >= 2 * elu_elems) ? 1 : 0;
    float* out_att = out + elu_elems;

    static int smem_set = 0;
    if (!smem_set) {
        cudaFuncSetAttribute(gat_pipe, cudaFuncAttributeMaxDynamicSharedMemorySize,
                             DYN_BYTES);
        smem_set = 1;
    }
    gat_pipe<<<NBLK, 256, DYN_BYTES>>>(inp, W, a, out, out_att, write_att);
}

// round 10
// speedup vs baseline: 1.1831x; 1.1831x over previous
#include <cuda_runtime.h>
#include <math.h>

#define NB 16
#define TT 12
#define AL 0.2f
#define PAD 65   // padded row stride (floats): conflict-free scalar row/col access

// Dynamic smem (floats): s_W[64*PAD] | s_src[64*PAD]
#define DYN_FLOATS (2 * 64 * PAD)
#define DYN_BYTES (DYN_FLOATS * 4)

__global__ __launch_bounds__(256) void gat_one(
    const float* __restrict__ inp,   // [NB,TT,64,64]
    const float* __restrict__ W,     // [64,64]
    const float* __restrict__ a,     // [128]
    float* __restrict__ out_elu,     // [NB,TT,64,64]
    float* __restrict__ out_att,     // [NB,TT,64,64]
    int write_att)
{
    extern __shared__ float sm[];
    float* s_W   = sm;               // [64][PAD]
    float* s_src = sm + 64 * PAD;    // [64][PAD]

    __shared__ __align__(16) float s_a [128];   // a_lo | a_hi
    __shared__ __align__(16) float s_A1[64];    // a_lo + a_hi
    __shared__ __align__(16) float s_WA[128];   // ti<6: WA1[64]; ti>=6: WAlo|WAhi
    __shared__ __align__(16) float s_cs[128];   // ti<6 own half colsums
    __shared__ __align__(16) float s_g [128];   // ti<6: g1[64]; ti>=6: g2a|g2b
    __shared__ __align__(16) float s_SW[128];   // ti<6: SW_lo|SW_hi
    __shared__ __align__(16) float s_p0[32], s_p1[32];
    __shared__ __align__(16) float s_att[32];
    __shared__ __align__(16) float s_wc[64], s_q[64];

    const int t   = threadIdx.x;
    const int bid = blockIdx.x, pair = bid >> 1, vb = bid & 1;
    const int n = pair / TT, ti = pair - n * TT;
    const bool first = (ti < 6);
    const int sl = first ? (2 * ti + vb) : (2 * (ti - 6) + vb);
    const float* src = inp + (size_t)(n * TT + sl) * 4096;
    const float* own = inp + (size_t)pair * 4096;

    // ---- Stage A: stage W + src (padded); a; (ti<6) own half colsums ----
    {
        const float4* Wg = (const float4*)W;
        const float4* Sg = (const float4*)src;
#pragma unroll
        for (int i = 0; i < 4; i++) {
            const int idx4 = t + i * 256;                // 1024 float4 = 64x64
            const int row = idx4 >> 4, col = (idx4 & 15) * 4;
            const int ba = row * PAD + col;
            const float4 wv = Wg[idx4];
            s_W[ba] = wv.x; s_W[ba + 1] = wv.y; s_W[ba + 2] = wv.z; s_W[ba + 3] = wv.w;
            const float4 sv = Sg[idx4];
            s_src[ba] = sv.x; s_src[ba + 1] = sv.y; s_src[ba + 2] = sv.z; s_src[ba + 3] = sv.w;
        }
        if (t < 128) s_a[t] = a[t];
        else if (t < 192) s_A1[t - 128] = a[t - 128] + a[t - 64];
        if (first && t >= 128) {
            const int d = t - 128;                    // 0..127
            const int hb = d >> 6, k = d & 63;
            const float* p = own + hb * 2048 + k;
            float c0 = 0.f, c1 = 0.f, c2 = 0.f, c3 = 0.f;
#pragma unroll
            for (int w = 0; w < 32; w += 4) {
                c0 += p[w * 64];
                c1 += p[(w + 1) * 64];
                c2 += p[(w + 2) * 64];
                c3 += p[(w + 3) * 64];
            }
            s_cs[d] = (c0 + c1) + (c2 + c3);
        }
    }
    __syncthreads();

    // ---- Stage B ----
    if (first) {
        if (t < 64) {                                // WA1[k] = W[k,:] . A1
            const int k = t;
            float s0 = 0.f, s1 = 0.f;
#pragma unroll
            for (int j = 0; j < 64; j += 2) {
                s0 = fmaf(s_W[k * PAD + j],     s_A1[j],     s0);
                s1 = fmaf(s_W[k * PAD + j + 1], s_A1[j + 1], s1);
            }
            s_WA[k] = s0 + s1;
        } else if (t >= 128) {                       // SW_c[j] = cs_c . W[:,j]
            const int d = t - 128, c = d >> 6, j = d & 63;
            const float* cs = s_cs + c * 64;
            float s0 = 0.f, s1 = 0.f;
#pragma unroll
            for (int k = 0; k < 64; k += 2) {
                s0 = fmaf(cs[k],     s_W[k * PAD + j],       s0);
                s1 = fmaf(cs[k + 1], s_W[(k + 1) * PAD + j], s1);
            }
            s_SW[c * 64 + j] = s0 + s1;
        }
    } else {
        if (t < 128) {                               // WA_c[k] = W[k,:] . a_c
            const int c = t >> 6, k = t & 63;
            const float* av = s_a + c * 64;
            float s0 = 0.f, s1 = 0.f;
#pragma unroll
            for (int j = 0; j < 64; j += 2) {
                s0 = fmaf(s_W[k * PAD + j],     av[j],     s0);
                s1 = fmaf(s_W[k * PAD + j + 1], av[j + 1], s1);
            }
            s_WA[c * 64 + k] = s0 + s1;
        }
    }
    __syncthreads();

    // ---- Stage C: g dots over the 64 src rows ----
    if (first) {
        if (t < 64) {
            const int u = t;
            float s0 = 0.f, s1 = 0.f;
#pragma unroll
            for (int k = 0; k < 64; k += 2) {
                s0 = fmaf(s_src[u * PAD + k],     s_WA[k],     s0);
                s1 = fmaf(s_src[u * PAD + k + 1], s_WA[k + 1], s1);
            }
            s_g[u] = s0 + s1;                        // g1[u]
        }
    } else {
        if (t < 128) {
            const int c = t >> 6, u = t & 63;
            const float* wav = s_WA + c * 64;
            float s0 = 0.f, s1 = 0.f;
#pragma unroll
            for (int k = 0; k < 64; k += 2) {
                s0 = fmaf(s_src[u * PAD + k],     wav[k],     s0);
                s1 = fmaf(s_src[u * PAD + k + 1], wav[k + 1], s1);
            }
            s_g[c * 64 + u] = s0 + s1;               // g2a[u] | g2b[u]
        }
    }
    __syncthreads();

    if (first) {
        // ---- Stage D: closed-form softmax ----
        if (t < 32) {
            float e0 = s_g[2 * t], e1 = s_g[2 * t + 1];
            e0 = (e0 > 0.f) ? e0 : AL * e0;
            e1 = (e1 > 0.f) ? e1 : AL * e1;
            const float m = fmaxf(e0, e1);
            const float p0 = __expf(e0 - m), p1 = __expf(e1 - m);
            const float inv = __frcp_rn(32.f * (p0 + p1));
            s_p0[t] = p0 * inv;
            s_p1[t] = p1 * inv;
        }
        __syncthreads();

        // ---- Stage E: outputs (32 rows x 64 cols) ----
        float4* oe4 = (float4*)(out_elu + (size_t)pair * 4096 + vb * 2048);
        float4* oa4 = (float4*)(out_att + (size_t)pair * 4096 + vb * 2048);
        const float4* Qlo = (const float4*)s_SW;
        const float4* Qhi = (const float4*)(s_SW + 64);
#pragma unroll
        for (int i = 0; i < 2; i++) {
            const int idx4 = t + i * 256;            // [0,512)
            const int r = idx4 >> 4, w4 = idx4 & 15;
            const float a0 = s_p0[r], a1 = s_p1[r];
            const float4 q0 = Qlo[w4], q1 = Qhi[w4];
            float4 rr;
            rr.x = fmaf(a0, q0.x, a1 * q1.x);
            rr.y = fmaf(a0, q0.y, a1 * q1.y);
            rr.z = fmaf(a0, q0.z, a1 * q1.z);
            rr.w = fmaf(a0, q0.w, a1 * q1.w);
            rr.x = (rr.x > 0.f) ? rr.x : (__expf(rr.x) - 1.f);
            rr.y = (rr.y > 0.f) ? rr.y : (__expf(rr.y) - 1.f);
            rr.z = (rr.z > 0.f) ? rr.z : (__expf(rr.z) - 1.f);
            rr.w = (rr.w > 0.f) ? rr.w : (__expf(rr.w) - 1.f);
            oe4[idx4] = rr;
            if (write_att) {
                const float av = (w4 < 8) ? a0 : a1;
                oa4[idx4] = make_float4(av, av, av, av);
            }
        }
    } else {
        // ---- Stage D: 32-wide softmax (warp 0) ----
        if (t < 32) {
            float e = s_g[2 * t] + s_g[64 + 2 * t + 1];  // g2a[2w'] + g2b[2w'+1]
            e = (e > 0.f) ? e : AL * e;
            float m = e;
#pragma unroll
            for (int o = 16; o; o >>= 1) m = fmaxf(m, __shfl_xor_sync(0xffffffffu, m, o));
            const float p = __expf(e - m);
            float ss = p;
#pragma unroll
            for (int o = 16; o; o >>= 1) ss += __shfl_xor_sync(0xffffffffu, ss, o);
            s_att[t] = p * __frcp_rn(2.f * ss);
        }
        __syncthreads();

        // ---- Stage E: weighted colsum of own slab, direct from global ----
        if (t < 64) {
            const int k = t;
            const float* p = own + k;
            float s0 = 0.f, s1 = 0.f, s2 = 0.f, s3 = 0.f;
#pragma unroll
            for (int w = 0; w < 32; w += 2) {
                s0 = fmaf(s_att[w],     p[w * 64],         s0);
                s1 = fmaf(s_att[w + 1], p[(w + 1) * 64],   s1);
                s2 = fmaf(s_att[w],     p[(w + 32) * 64],  s2);
                s3 = fmaf(s_att[w + 1], p[(w + 33) * 64],  s3);
            }
            s_wc[k] = (s0 + s1) + (s2 + s3);
        }
        __syncthreads();

        // ---- Stage F: q[j] = wc . W[:,j], fold ELU ----
        if (t < 64) {
            const int j = t;
            float s0 = 0.f, s1 = 0.f;
#pragma unroll
            for (int k = 0; k < 64; k += 2) {
                s0 = fmaf(s_wc[k],     s_W[k * PAD + j],       s0);
                s1 = fmaf(s_wc[k + 1], s_W[(k + 1) * PAD + j], s1);
            }
            const float qv = s0 + s1;
            s_q[j] = (qv > 0.f) ? qv : (__expf(qv) - 1.f);
        }
        __syncthreads();

        // ---- Stage G: broadcast outputs ----
        float4* oe4 = (float4*)(out_elu + (size_t)pair * 4096 + vb * 2048);
        float4* oa4 = (float4*)(out_att + (size_t)pair * 4096 + vb * 2048);
        const float4* Q4 = (const float4*)s_q;
        const float4* A4 = (const float4*)s_att;
#pragma unroll
        for (int i = 0; i < 2; i++) {
            const int idx4 = t + i * 256;
            const int w4 = idx4 & 15;
            oe4[idx4] = Q4[w4];
            if (write_att) oa4[idx4] = A4[w4 & 7];
        }
    }
}

extern "C" void kernel_launch(void* const* d_in, const int* in_sizes, int n_in,
                              void* d_out, int out_size)
{
    const float* inp = (const float*)d_in[0];   // [16,12,64,64]
    // d_in[1] = adj — dead in the reference
    const float* W   = (const float*)d_in[2];   // [64,64]
    const float* a   = (const float*)d_in[3];   // [128,1]
    float* out = (float*)d_out;

    const int elu_elems = NB * TT * 64 * 64;    // 786432
    const int write_att = (out_size >= 2 * elu_elems) ? 1 : 0;
    float* out_att = out + elu_elems;

    gat_one<<<NB * TT * 2, 256, DYN_BYTES>>>(inp, W, a, out, out_att, write_att);
}

// round 11
// speedup vs baseline: 1.1866x; 1.0029x over previous
#include <cuda_runtime.h>
#include <math.h>

#define NB 16
#define TT 12
#define AL 0.2f
#define PAD 65   // padded row stride (floats): conflict-free row/col access

// Dynamic smem (floats): s_W[64*PAD] | s_src[64*PAD]
#define DYN_FLOATS (2 * 64 * PAD)
#define DYN_BYTES (DYN_FLOATS * 4)

__global__ __launch_bounds__(256) void gat_one(
    const float* __restrict__ inp,   // [NB,TT,64,64]
    const float* __restrict__ W,     // [64,64]
    const float* __restrict__ a,     // [128]
    float* __restrict__ out_elu,     // [NB,TT,64,64]
    float* __restrict__ out_att,     // [NB,TT,64,64]
    int write_att)
{
    extern __shared__ float sm[];
    float* s_W   = sm;               // [64][PAD]
    float* s_src = sm + 64 * PAD;    // [64][PAD]

    __shared__ __align__(16) float s_WA[128];   // ti<6: WA1[64]; ti>=6: WAlo|WAhi
    __shared__ __align__(16) float s_cs[128];   // ti<6 own half colsums
    __shared__ __align__(16) float s_g [128];   // ti<6: g1[64]; ti>=6: g2a|g2b
    __shared__ __align__(16) float s_SW[128];   // ti<6: SW_lo|SW_hi
    __shared__ __align__(16) float s_att[32];   // ti>=6 att (for out_att)
    __shared__ __align__(16) float s_wc[64], s_q[64];

    const int t   = threadIdx.x;
    const int bid = blockIdx.x, pair = bid >> 1, vb = bid & 1;
    const int n = pair / TT, ti = pair - n * TT;
    const bool first = (ti < 6);
    const int sl = first ? (2 * ti + vb) : (2 * (ti - 6) + vb);
    const float* src = inp + (size_t)(n * TT + sl) * 4096;
    const float* own = inp + (size_t)pair * 4096;

    const int warp = t >> 5, ln = t & 31;
    const int rq = ln >> 2, q = ln & 3;          // 4 lanes per row for WA dots

    // ============ Stage A: stage W+src (padded); WA from global; cs ============
    {
        const float4* Wg = (const float4*)W;
        const float4* Sg = (const float4*)src;
#pragma unroll
        for (int i = 0; i < 4; i++) {
            const int idx4 = t + i * 256;                // 1024 float4 = 64x64
            const int row = idx4 >> 4, col = (idx4 & 15) * 4;
            const int ba = row * PAD + col;
            const float4 wv = Wg[idx4];
            s_W[ba] = wv.x; s_W[ba + 1] = wv.y; s_W[ba + 2] = wv.z; s_W[ba + 3] = wv.w;
            const float4 sv = Sg[idx4];
            s_src[ba] = sv.x; s_src[ba + 1] = sv.y; s_src[ba + 2] = sv.z; s_src[ba + 3] = sv.w;
        }
        // WA row-dots straight from global (overlaps staging latency):
        // warp w handles rows k = 8w..8w+7; 4 lanes per row.
        {
            const int k = warp * 8 + rq;
            const float4* Al4 = (const float4*)a;
            const float4* Ah4 = (const float4*)(a + 64);
            float lo = 0.f, hi = 0.f;
#pragma unroll
            for (int i = 0; i < 4; i++) {
                const float4 wv = Wg[k * 16 + q * 4 + i];
                const float4 al = Al4[q * 4 + i];
                const float4 ah = Ah4[q * 4 + i];
                lo += wv.x * al.x + wv.y * al.y + wv.z * al.z + wv.w * al.w;
                hi += wv.x * ah.x + wv.y * ah.y + wv.z * ah.z + wv.w * ah.w;
            }
#pragma unroll
            for (int o = 1; o <= 2; o <<= 1) {
                lo += __shfl_xor_sync(0xffffffffu, lo, o);
                hi += __shfl_xor_sync(0xffffffffu, hi, o);
            }
            if (q == 0) {
                if (first) s_WA[k] = lo + hi;
                else       { s_WA[k] = lo; s_WA[64 + k] = hi; }
            }
        }
        // ti<6: own half colsums direct from global (t<128)
        if (first && t < 128) {
            const int hb = t >> 6, k = t & 63;
            const float* p = own + hb * 2048 + k;
            float c0 = 0.f, c1 = 0.f, c2 = 0.f, c3 = 0.f;
#pragma unroll
            for (int w = 0; w < 32; w += 4) {
                c0 += p[w * 64];
                c1 += p[(w + 1) * 64];
                c2 += p[(w + 2) * 64];
                c3 += p[(w + 3) * 64];
            }
            s_cs[t] = (c0 + c1) + (c2 + c3);
        }
    }
    __syncthreads();

    if (first) {
        // ======== Stage B: g1 (t<64)  ||  SW matvecs (t>=128) ========
        if (t < 64) {
            const int u = t;
            float s0 = 0.f, s1 = 0.f;
#pragma unroll
            for (int k = 0; k < 64; k += 2) {
                s0 = fmaf(s_src[u * PAD + k],     s_WA[k],     s0);
                s1 = fmaf(s_src[u * PAD + k + 1], s_WA[k + 1], s1);
            }
            s_g[u] = s0 + s1;                        // g1[u]
        } else if (t >= 128) {
            const int d = t - 128, c = d >> 6, j = d & 63;
            const float* cs = s_cs + c * 64;
            float s0 = 0.f, s1 = 0.f;
#pragma unroll
            for (int k = 0; k < 64; k += 2) {
                s0 = fmaf(cs[k],     s_W[k * PAD + j],       s0);
                s1 = fmaf(cs[k + 1], s_W[(k + 1) * PAD + j], s1);
            }
            s_SW[c * 64 + j] = s0 + s1;              // SW_lo | SW_hi
        }
        __syncthreads();

        // ======== Stage C: outputs with inlined closed-form softmax ========
        float4* oe4 = (float4*)(out_elu + (size_t)pair * 4096 + vb * 2048);
        float4* oa4 = (float4*)(out_att + (size_t)pair * 4096 + vb * 2048);
        const float4* Qlo = (const float4*)s_SW;
        const float4* Qhi = (const float4*)(s_SW + 64);
#pragma unroll
        for (int i = 0; i < 2; i++) {
            const int idx4 = t + i * 256;            // [0,512)
            const int r = idx4 >> 4, w4 = idx4 & 15;
            // inline per-row probs (tiny: 2 LDS + 2 exp + 1 rcp)
            float e0 = s_g[2 * r], e1 = s_g[2 * r + 1];
            e0 = (e0 > 0.f) ? e0 : AL * e0;
            e1 = (e1 > 0.f) ? e1 : AL * e1;
            const float m = fmaxf(e0, e1);
            const float p0 = __expf(e0 - m), p1 = __expf(e1 - m);
            const float inv = __frcp_rn(32.f * (p0 + p1));
            const float a0 = p0 * inv, a1 = p1 * inv;
            const float4 q0 = Qlo[w4], q1 = Qhi[w4];
            float4 rr;
            rr.x = fmaf(a0, q0.x, a1 * q1.x);
            rr.y = fmaf(a0, q0.y, a1 * q1.y);
            rr.z = fmaf(a0, q0.z, a1 * q1.z);
            rr.w = fmaf(a0, q0.w, a1 * q1.w);
            rr.x = (rr.x > 0.f) ? rr.x : (__expf(rr.x) - 1.f);
            rr.y = (rr.y > 0.f) ? rr.y : (__expf(rr.y) - 1.f);
            rr.z = (rr.z > 0.f) ? rr.z : (__expf(rr.z) - 1.f);
            rr.w = (rr.w > 0.f) ? rr.w : (__expf(rr.w) - 1.f);
            oe4[idx4] = rr;
            if (write_att) {
                const float av = (w4 < 8) ? a0 : a1;
                oa4[idx4] = make_float4(av, av, av, av);
            }
        }
    } else {
        // ======== Stage B: g2a | g2b dots (t<128) ========
        if (t < 128) {
            const int c = t >> 6, u = t & 63;
            const float* wav = s_WA + c * 64;
            float s0 = 0.f, s1 = 0.f;
#pragma unroll
            for (int k = 0; k < 64; k += 2) {
                s0 = fmaf(s_src[u * PAD + k],     wav[k],     s0);
                s1 = fmaf(s_src[u * PAD + k + 1], wav[k + 1], s1);
            }
            s_g[c * 64 + u] = s0 + s1;               // g2a[u] | g2b[u]
        }
        __syncthreads();

        // ======== Stage C: per-warp softmax (registers) + wc ========
        float att;
        {
            float e = s_g[2 * ln] + s_g[64 + 2 * ln + 1];
            e = (e > 0.f) ? e : AL * e;
            float m = e;
#pragma unroll
            for (int o = 16; o; o >>= 1) m = fmaxf(m, __shfl_xor_sync(0xffffffffu, m, o));
            const float p = __expf(e - m);
            float ss = p;
#pragma unroll
            for (int o = 16; o; o >>= 1) ss += __shfl_xor_sync(0xffffffffu, ss, o);
            att = p * __frcp_rn(2.f * ss);
            if (t < 32) s_att[t] = att;              // for out_att broadcast
        }
        if (t < 64) {                                // wc[k], warps 0-1 have att
            const int k = t;
            const float* p = own + k;
            float s0 = 0.f, s1 = 0.f, s2 = 0.f, s3 = 0.f;
#pragma unroll
            for (int w = 0; w < 32; w += 2) {
                const float aw0 = __shfl_sync(0xffffffffu, att, w);
                const float aw1 = __shfl_sync(0xffffffffu, att, w + 1);
                s0 = fmaf(aw0, p[w * 64],        s0);
                s1 = fmaf(aw1, p[(w + 1) * 64],  s1);
                s2 = fmaf(aw0, p[(w + 32) * 64], s2);
                s3 = fmaf(aw1, p[(w + 33) * 64], s3);
            }
            s_wc[k] = (s0 + s1) + (s2 + s3);
        }
        __syncthreads();

        // ======== Stage D: q[j] = wc . W[:,j], fold ELU ========
        if (t < 64) {
            const int j = t;
            float s0 = 0.f, s1 = 0.f;
#pragma unroll
            for (int k = 0; k < 64; k += 2) {
                s0 = fmaf(s_wc[k],     s_W[k * PAD + j],       s0);
                s1 = fmaf(s_wc[k + 1], s_W[(k + 1) * PAD + j], s1);
            }
            const float qv = s0 + s1;
            s_q[j] = (qv > 0.f) ? qv : (__expf(qv) - 1.f);
        }
        __syncthreads();

        // ======== Stage E: broadcast outputs ========
        float4* oe4 = (float4*)(out_elu + (size_t)pair * 4096 + vb * 2048);
        float4* oa4 = (float4*)(out_att + (size_t)pair * 4096 + vb * 2048);
        const float4* Q4 = (const float4*)s_q;
        const float4* A4 = (const float4*)s_att;
#pragma unroll
        for (int i = 0; i < 2; i++) {
            const int idx4 = t + i * 256;
            const int w4 = idx4 & 15;
            oe4[idx4] = Q4[w4];
            if (write_att) oa4[idx4] = A4[w4 & 7];
        }
    }
}

extern "C" void kernel_launch(void* const* d_in, const int* in_sizes, int n_in,
                              void* d_out, int out_size)
{
    const float* inp = (const float*)d_in[0];   // [16,12,64,64]
    // d_in[1] = adj — dead in the reference
    const float* W   = (const float*)d_in[2];   // [64,64]
    const float* a   = (const float*)d_in[3];   // [128,1]
    float* out = (float*)d_out;

    const int elu_elems = NB * TT * 64 * 64;    // 786432
    const int write_att = (out_size >= 2 * elu_elems) ? 1 : 0;
    float* out_att = out + elu_elems;

    gat_one<<<NB * TT * 2, 256, DYN_BYTES>>>(inp, W, a, out, out_att, write_att);
}

// round 12
// speedup vs baseline: 1.2149x; 1.0239x over previous
#include <cuda_runtime.h>
#include <math.h>

#define NB 16
#define TT 12
#define AL 0.2f
#define PAD 65   // padded row stride (floats): conflict-free row/col access

// Dynamic smem (floats): s_W[64*PAD] | s_src[64*PAD]
#define DYN_FLOATS (2 * 64 * PAD)
#define DYN_BYTES (DYN_FLOATS * 4)

__global__ __launch_bounds__(256) void gat_one(
    const float* __restrict__ inp,   // [NB,TT,64,64]
    const float* __restrict__ W,     // [64,64]
    const float* __restrict__ a,     // [128]
    float* __restrict__ out_elu,     // [NB,TT,64,64]
    float* __restrict__ out_att,     // [NB,TT,64,64]
    int write_att)
{
    extern __shared__ float sm[];
    float* s_W   = sm;               // [64][PAD]
    float* s_src = sm + 64 * PAD;    // [64][PAD]

    __shared__ __align__(16) float s_a [128];   // a_lo | a_hi
    __shared__ __align__(16) float s_A1[64];    // a_lo + a_hi
    __shared__ __align__(16) float s_WA[128];   // ti<6: WA1[64]; ti>=6: WAlo|WAhi
    __shared__ __align__(16) float s_cs[128];   // ti<6 own half colsums
    __shared__ __align__(16) float s_g [128];   // ti<6: g1[64]; ti>=6: g2a|g2b
    __shared__ __align__(16) float s_SW[128];   // ti<6: SW_lo|SW_hi
    __shared__ __align__(16) float s_p0[32], s_p1[32];
    __shared__ __align__(16) float s_att[32];
    __shared__ __align__(16) float s_wc[64], s_q[64];

    const int t   = threadIdx.x;
    const int bid = blockIdx.x, pair = bid >> 1, vb = bid & 1;
    const int n = pair / TT, ti = pair - n * TT;
    const bool first = (ti < 6);
    const int sl = first ? (2 * ti + vb) : (2 * (ti - 6) + vb);
    const float* src = inp + (size_t)(n * TT + sl) * 4096;
    const float* own = inp + (size_t)pair * 4096;

    // ---- Stage A: stage W + src (padded, bid-staggered); a; (ti<6) colsums ----
    {
        const float4* Wg = (const float4*)W;
        const float4* Sg = (const float4*)src;
        const int i0 = bid & 3;                       // stagger the LDG burst
#pragma unroll
        for (int ii = 0; ii < 4; ii++) {
            const int i = (ii + i0) & 3;
            const int idx4 = t + i * 256;             // 1024 float4 = 64x64
            const int row = idx4 >> 4, col = (idx4 & 15) * 4;
            const int ba = row * PAD + col;
            const float4 wv = Wg[idx4];
            s_W[ba] = wv.x; s_W[ba + 1] = wv.y; s_W[ba + 2] = wv.z; s_W[ba + 3] = wv.w;
            const float4 sv = Sg[idx4];
            s_src[ba] = sv.x; s_src[ba + 1] = sv.y; s_src[ba + 2] = sv.z; s_src[ba + 3] = sv.w;
        }
        if (t < 128) s_a[t] = a[t];
        else if (t < 192) s_A1[t - 128] = a[t - 128] + a[t - 64];
        if (first && t >= 128) {
            const int d = t - 128;                    // 0..127
            const int hb = d >> 6, k = d & 63;
            const float* p = own + hb * 2048 + k;
            const int w0 = (bid & 7) * 4;             // stagger colsum start
            float c0 = 0.f, c1 = 0.f, c2 = 0.f, c3 = 0.f;
#pragma unroll
            for (int wi = 0; wi < 32; wi += 4) {
                const int w = (wi + w0) & 31;
                c0 += p[w * 64];
                c1 += p[((w + 1) & 31) * 64];
                c2 += p[((w + 2) & 31) * 64];
                c3 += p[((w + 3) & 31) * 64];
            }
            s_cs[d] = (c0 + c1) + (c2 + c3);
        }
    }
    __syncthreads();

    // ---- Stage B ----
    if (first) {
        if (t < 64) {                                // WA1[k] = W[k,:] . A1
            const int k = t;
            float s0 = 0.f, s1 = 0.f;
#pragma unroll
            for (int j = 0; j < 64; j += 2) {
                s0 = fmaf(s_W[k * PAD + j],     s_A1[j],     s0);
                s1 = fmaf(s_W[k * PAD + j + 1], s_A1[j + 1], s1);
            }
            s_WA[k] = s0 + s1;
        } else if (t >= 128) {                       // SW_c[j] = cs_c . W[:,j]
            const int d = t - 128, c = d >> 6, j = d & 63;
            const float* cs = s_cs + c * 64;
            float s0 = 0.f, s1 = 0.f;
#pragma unroll
            for (int k = 0; k < 64; k += 2) {
                s0 = fmaf(cs[k],     s_W[k * PAD + j],       s0);
                s1 = fmaf(cs[k + 1], s_W[(k + 1) * PAD + j], s1);
            }
            s_SW[c * 64 + j] = s0 + s1;
        }
    } else {
        if (t < 128) {                               // WA_c[k] = W[k,:] . a_c
            const int c = t >> 6, k = t & 63;
            const float* av = s_a + c * 64;
            float s0 = 0.f, s1 = 0.f;
#pragma unroll
            for (int j = 0; j < 64; j += 2) {
                s0 = fmaf(s_W[k * PAD + j],     av[j],     s0);
                s1 = fmaf(s_W[k * PAD + j + 1], av[j + 1], s1);
            }
            s_WA[c * 64 + k] = s0 + s1;
        }
    }
    __syncthreads();

    // ---- Stage C: g dots over the 64 src rows ----
    if (first) {
        if (t < 64) {
            const int u = t;
            float s0 = 0.f, s1 = 0.f;
#pragma unroll
            for (int k = 0; k < 64; k += 2) {
                s0 = fmaf(s_src[u * PAD + k],     s_WA[k],     s0);
                s1 = fmaf(s_src[u * PAD + k + 1], s_WA[k + 1], s1);
            }
            s_g[u] = s0 + s1;                        // g1[u]
        }
    } else {
        if (t < 128) {
            const int c = t >> 6, u = t & 63;
            const float* wav = s_WA + c * 64;
            float s0 = 0.f, s1 = 0.f;
#pragma unroll
            for (int k = 0; k < 64; k += 2) {
                s0 = fmaf(s_src[u * PAD + k],     wav[k],     s0);
                s1 = fmaf(s_src[u * PAD + k + 1], wav[k + 1], s1);
            }
            s_g[c * 64 + u] = s0 + s1;               // g2a[u] | g2b[u]
        }
    }
    __syncthreads();

    if (first) {
        // ---- Stage D: closed-form softmax ----
        if (t < 32) {
            float e0 = s_g[2 * t], e1 = s_g[2 * t + 1];
            e0 = (e0 > 0.f) ? e0 : AL * e0;
            e1 = (e1 > 0.f) ? e1 : AL * e1;
            const float m = fmaxf(e0, e1);
            const float p0 = __expf(e0 - m), p1 = __expf(e1 - m);
            const float inv = __frcp_rn(32.f * (p0 + p1));
            s_p0[t] = p0 * inv;
            s_p1[t] = p1 * inv;
        }
        __syncthreads();

        // ---- Stage E: outputs (32 rows x 64 cols) ----
        float4* oe4 = (float4*)(out_elu + (size_t)pair * 4096 + vb * 2048);
        float4* oa4 = (float4*)(out_att + (size_t)pair * 4096 + vb * 2048);
        const float4* Qlo = (const float4*)s_SW;
        const float4* Qhi = (const float4*)(s_SW + 64);
#pragma unroll
        for (int i = 0; i < 2; i++) {
            const int idx4 = t + i * 256;            // [0,512)
            const int r = idx4 >> 4, w4 = idx4 & 15;
            const float a0 = s_p0[r], a1 = s_p1[r];
            const float4 q0 = Qlo[w4], q1 = Qhi[w4];
            float4 rr;
            rr.x = fmaf(a0, q0.x, a1 * q1.x);
            rr.y = fmaf(a0, q0.y, a1 * q1.y);
            rr.z = fmaf(a0, q0.z, a1 * q1.z);
            rr.w = fmaf(a0, q0.w, a1 * q1.w);
            rr.x = (rr.x > 0.f) ? rr.x : (__expf(rr.x) - 1.f);
            rr.y = (rr.y > 0.f) ? rr.y : (__expf(rr.y) - 1.f);
            rr.z = (rr.z > 0.f) ? rr.z : (__expf(rr.z) - 1.f);
            rr.w = (rr.w > 0.f) ? rr.w : (__expf(rr.w) - 1.f);
            oe4[idx4] = rr;
            if (write_att) {
                const float av = (w4 < 8) ? a0 : a1;
                oa4[idx4] = make_float4(av, av, av, av);
            }
        }
    } else {
        // ---- Stage D: 32-wide softmax (warp 0) ----
        if (t < 32) {
            float e = s_g[2 * t] + s_g[64 + 2 * t + 1];  // g2a[2w'] + g2b[2w'+1]
            e = (e > 0.f) ? e : AL * e;
            float m = e;
#pragma unroll
            for (int o = 16; o; o >>= 1) m = fmaxf(m, __shfl_xor_sync(0xffffffffu, m, o));
            const float p = __expf(e - m);
            float ss = p;
#pragma unroll
            for (int o = 16; o; o >>= 1) ss += __shfl_xor_sync(0xffffffffu, ss, o);
            s_att[t] = p * __frcp_rn(2.f * ss);
        }
        __syncthreads();

        // ---- Stage E: weighted colsum of own slab (2 threads per column) ----
        if (t < 128) {
            const int k = t >> 1, pp = t & 1;
            const float* p = own + k + pp * 16 * 64;     // rows pp*16..pp*16+15 (+32)
            float s0 = 0.f, s1 = 0.f, s2 = 0.f, s3 = 0.f;
#pragma unroll
            for (int w = 0; w < 16; w += 2) {
                const float aw0 = s_att[pp * 16 + w];
                const float aw1 = s_att[pp * 16 + w + 1];
                s0 = fmaf(aw0, p[w * 64],        s0);
                s1 = fmaf(aw1, p[(w + 1) * 64],  s1);
                s2 = fmaf(aw0, p[(w + 32) * 64], s2);
                s3 = fmaf(aw1, p[(w + 33) * 64], s3);
            }
            float s = (s0 + s1) + (s2 + s3);
            s += __shfl_xor_sync(0xffffffffu, s, 1);
            if (!pp) s_wc[k] = s;
        }
        __syncthreads();

        // ---- Stage F: q[j] = wc . W[:,j], fold ELU (2 threads per j) ----
        if (t < 128) {
            const int j = t >> 1, pp = t & 1;
            float s0 = 0.f, s1 = 0.f;
#pragma unroll
            for (int i = 0; i < 32; i += 2) {
                const int ka = pp * 32 + i, kb = ka + 1;
                s0 = fmaf(s_wc[ka], s_W[ka * PAD + j], s0);
                s1 = fmaf(s_wc[kb], s_W[kb * PAD + j], s1);
            }
            float s = s0 + s1;
            s += __shfl_xor_sync(0xffffffffu, s, 1);
            if (!pp) s_q[j] = (s > 0.f) ? s : (__expf(s) - 1.f);
        }
        __syncthreads();

        // ---- Stage G: broadcast outputs ----
        float4* oe4 = (float4*)(out_elu + (size_t)pair * 4096 + vb * 2048);
        float4* oa4 = (float4*)(out_att + (size_t)pair * 4096 + vb * 2048);
        const float4* Q4 = (const float4*)s_q;
        const float4* A4 = (const float4*)s_att;
#pragma unroll
        for (int i = 0; i < 2; i++) {
            const int idx4 = t + i * 256;
            const int w4 = idx4 & 15;
            oe4[idx4] = Q4[w4];
            if (write_att) oa4[idx4] = A4[w4 & 7];
        }
    }
}

extern "C" void kernel_launch(void* const* d_in, const int* in_sizes, int n_in,
                              void* d_out, int out_size)
{
    const float* inp = (const float*)d_in[0];   // [16,12,64,64]
    // d_in[1] = adj — dead in the reference
    const float* W   = (const float*)d_in[2];   // [64,64]
    const float* a   = (const float*)d_in[3];   // [128,1]
    float* out = (float*)d_out;

    const int elu_elems = NB * TT * 64 * 64;    // 786432
    const int write_att = (out_size >= 2 * elu_elems) ? 1 : 0;
    float* out_att = out + elu_elems;

    gat_one<<<NB * TT * 2, 256, DYN_BYTES>>>(inp, W, a, out, out_att, write_att);
}